// round 16
// baseline (speedup 1.0000x reference)
#include <cuda_runtime.h>
#include <cooperative_groups.h>
#include <math.h>

namespace cg = cooperative_groups;

#define ROW_LEN   65536
#define CSIZE     8
#define SEG       (ROW_LEN / CSIZE)     // 8192 elements per CTA
#define THREADS   256
#define TPT       32                    // thread streams [e0, e0+32) in updates
#define JOFF      8

#define TREND_SCALING       0.6f
#define DETAIL_PRESERVATION 0.85f
#define SPIKE_THRESHOLD     3.5f
#define SPIKE_DAMPING       0.35f
#define EPS_STD             1e-6f
#define F_KEEP   DETAIL_PRESERVATION                      // 0.85
#define F_DAMP   (DETAIL_PRESERVATION * SPIKE_DAMPING)    // 0.2975
#define C5       ((1.0f - TREND_SCALING) * 0.2f)          // 0.08
#define C11      (TREND_SCALING / 11.0f)

// XOR swizzle: permutes quads within 128B rows by row index; all float4
// LDS/STS at per-lane stride of 32 floats are bank-conflict-free.
__device__ __forceinline__ int SX(int j) { return j ^ ((j >> 3) & 0x1C); }

// smem layout (floats): data cells j in [0, 8224), then scratch
#define OFF_RED     8224                // 17 floats: warp partials + thr
#define OFF_MAIL    8244                // 16 floats: per-rank (s, ss)
#define SMEM_FLOATS 8260
#define SMEM_BYTES  (SMEM_FLOATS * 4)

__device__ __forceinline__ float4 LD4(const float* sm, int j) {
    return *reinterpret_cast<const float4*>(sm + SX(j));
}
__device__ __forceinline__ void ST4(float* sm, int j, float4 v) {
    *reinterpret_cast<float4*>(sm + SX(j)) = v;
}

// reflect over the full row [0, ROW_LEN)
__device__ __forceinline__ int rrow(int g) {
    if (g < 0) g = -g;
    if (g >= ROW_LEN) g = 2 * ROW_LEN - 2 - g;
    return g;
}

// cluster-wide threshold from per-thread (s, ss); deterministic order.
__device__ __forceinline__ float cluster_threshold(
    cg::cluster_group& cl, float s, float ss, float* sm, int rank, int tid)
{
    float* red  = sm + OFF_RED;
    float* mail = sm + OFF_MAIL;
    const unsigned m = 0xffffffffu;
    #pragma unroll
    for (int off = 16; off; off >>= 1) {
        s  += __shfl_down_sync(m, s,  off);
        ss += __shfl_down_sync(m, ss, off);
    }
    const int wid = tid >> 5, lid = tid & 31;
    if (lid == 0) { red[wid] = s; red[8 + wid] = ss; }
    __syncthreads();
    if (tid == 0) {
        float bs = 0.f, bss = 0.f;
        #pragma unroll
        for (int w = 0; w < 8; w++) { bs += red[w]; bss += red[8 + w]; }
        #pragma unroll
        for (int r2 = 0; r2 < CSIZE; r2++) {
            float* pm = cl.map_shared_rank(sm, r2) + OFF_MAIL;
            pm[2 * rank]     = bs;
            pm[2 * rank + 1] = bss;
        }
    }
    cl.sync();
    if (tid == 0) {
        float cs = 0.f, css = 0.f;
        #pragma unroll
        for (int r2 = 0; r2 < CSIZE; r2++) {
            cs  += mail[2 * r2];
            css += mail[2 * r2 + 1];
        }
        const float n = (float)ROW_LEN;
        float var = (css - cs * cs / n) / (n - 1.0f);
        var = fmaxf(var, 0.0f);
        red[16] = fmaxf(sqrtf(var), EPS_STD) * SPIKE_THRESHOLD;
    }
    __syncthreads();
    return red[16];
}

#define EMIT(dst, cur)                                             \
    do {                                                           \
        float _r = (cur) - 0.2f * s5;                              \
        float _f = (fabsf(_r) > thr) ? F_DAMP : F_KEEP;            \
        float _c = fmaf(s5, C5, s11 * C11);                        \
        dst = fmaf(_r, _f, _c);                                    \
    } while (0)

__global__ void __launch_bounds__(THREADS, 4) __cluster_dims__(CSIZE, 1, 1)
fd16_kernel(const float* __restrict__ x, float* __restrict__ out)
{
    extern __shared__ float sm[];
    cg::cluster_group cl = cg::this_cluster();
    const int rank = (int)cl.block_rank();
    const int row  = blockIdx.x / CSIZE;
    const int tid  = threadIdx.x;
    const int lane = tid & 31;
    const float* xr = x + (size_t)row * ROW_LEN;
    const int e0   = rank * SEG + tid * TPT;   // row-local element 0 (updates)
    const int base = JOFF + tid * TPT;         // smem cell of element 0
    const unsigned FULL = 0xffffffffu;

    // ===== stage (full-MLP batched loads) + stats1 from registers ===========
    float s1 = 0.f, ss1 = 0.f;
    {
        float4 v[8];
        // 8 independent LDG.128 — full memory-level parallelism
        #pragma unroll
        for (int g = 0; g < 8; g++) {
            int q = g * (THREADS * 4) + tid * 4;
            v[g] = *reinterpret_cast<const float4*>(xr + rank * SEG + q);
        }
        #pragma unroll
        for (int g = 0; g < 8; g++) {
            int q = g * (THREADS * 4) + tid * 4;
            ST4(sm, JOFF + q, v[g]);
        }
        // quad-reset stats over the staged registers; +-2 halo via lane shfl
        // (neighbor lane's same-g quad is q +- 4); warp-edge lanes: global LDG
        #pragma unroll
        for (int g = 0; g < 8; g++) {
            const int ge = rank * SEG + g * (THREADS * 4) + tid * 4;
            float4 c = v[g];
            float hl0 = __shfl_up_sync(FULL, c.z, 1);      // e[ge-2]
            float hl1 = __shfl_up_sync(FULL, c.w, 1);      // e[ge-1]
            float hr0 = __shfl_down_sync(FULL, c.x, 1);    // e[ge+4]
            float hr1 = __shfl_down_sync(FULL, c.y, 1);    // e[ge+5]
            if (lane == 0)  { hl0 = xr[rrow(ge - 2)]; hl1 = xr[rrow(ge - 1)]; }
            if (lane == 31) { hr0 = xr[rrow(ge + 4)]; hr1 = xr[rrow(ge + 5)]; }

            float s5 = (hl0 + hl1) + (c.x + c.y) + c.z;    // fresh per quad
            float r;
            r = c.x - 0.2f * s5; s1 += r; ss1 += r * r;
            s5 += c.w - hl0;
            r = c.y - 0.2f * s5; s1 += r; ss1 += r * r;
            s5 += hr0 - hl1;
            r = c.z - 0.2f * s5; s1 += r; ss1 += r * r;
            s5 += hr1 - c.x;
            r = c.w - 0.2f * s5; s1 += r; ss1 += r * r;
        }
    }
    const float thr1 = cluster_threshold(cl, s1, ss1, sm, rank, tid);  // sync #1
    // (its internal __syncthreads makes staged x visible CTA-wide)

    // ===== update1: in-place; edge threads take x halos from global =========
    {
        const float thr = thr1;
        float4 lm, l, r6, r7;
        if (tid == 0) {
            lm = make_float4(xr[rrow(e0-8)], xr[rrow(e0-7)], xr[rrow(e0-6)], xr[rrow(e0-5)]);
            l  = make_float4(xr[rrow(e0-4)], xr[rrow(e0-3)], xr[rrow(e0-2)], xr[rrow(e0-1)]);
        } else {
            lm = LD4(sm, base - 8);
            l  = LD4(sm, base - 4);
        }
        if (tid == THREADS - 1) {
            r6 = make_float4(xr[rrow(e0+32)], xr[rrow(e0+33)], xr[rrow(e0+34)], xr[rrow(e0+35)]);
            r7 = make_float4(xr[rrow(e0+36)], xr[rrow(e0+37)], xr[rrow(e0+38)], xr[rrow(e0+39)]);
        } else {
            r6 = LD4(sm, base + 32);
            r7 = LD4(sm, base + 36);
        }
        __syncthreads();   // all cross-thread old-x reads complete before stores

        float4 a = LD4(sm, base);
        float4 b = LD4(sm, base + 4);
        float4 qm1 = l;
        float  em5 = lm.w;

        #pragma unroll
        for (int k = 0; k < 8; k++) {
            float4 n = (k < 6) ? LD4(sm, base + 4 * k + 8)
                               : ((k == 6) ? r6 : r7);
            float s5  = (qm1.z + qm1.w) + (a.x + a.y) + a.z;
            float s11 = ((em5 + qm1.x) + (qm1.y + qm1.z)) +
                        ((qm1.w + a.x) + (a.y + a.z)) +
                        ((a.w + b.x) + b.y);
            float4 o4;
            EMIT(o4.x, a.x);  s5 += a.w - qm1.z;  s11 += b.z - em5;
            EMIT(o4.y, a.y);  s5 += b.x - qm1.w;  s11 += b.w - qm1.x;
            EMIT(o4.z, a.z);  s5 += b.y - a.x;    s11 += n.x - qm1.y;
            EMIT(o4.w, a.w);
            ST4(sm, base + 4 * k, o4);
            em5 = qm1.w; qm1 = a; a = b; b = n;
        }
    }
    cl.sync();   // sync #2: current2 visible cluster-wide

    // ===== halo fill for current2: 8 left / 8 right (5 meaningful + pad) =====
    if (tid < 8) {
        int d = 8 - tid;                 // 8..1 ; cell e[-d]
        float lv = 0.f;
        if (d <= 5) {
            if (rank == 0) {
                lv = sm[SX(JOFF + d)];                   // reflect -d -> d
            } else {
                const float* peer = cl.map_shared_rank(sm, rank - 1);
                lv = peer[SX(JOFF + SEG - d)];
            }
        }
        sm[SX(JOFF - d)] = lv;

        int k = tid;                     // 0..7 ; cell e[SEG+k]
        float rv = 0.f;
        if (k <= 4) {
            if (rank == CSIZE - 1) {
                rv = sm[SX(JOFF + SEG - 2 - k)];         // reflect L+k -> L-2-k
            } else {
                const float* peer = cl.map_shared_rank(sm, rank + 1);
                rv = peer[SX(JOFF + k)];
            }
        }
        sm[SX(JOFF + SEG + k)] = rv;
    }
    __syncthreads();

    // ===== stats2: quad-reset LDS stream (halo cells cover edges) ============
    float s2 = 0.f, ss2 = 0.f;
    {
        float4 km1 = LD4(sm, base - 4);
        float4 c   = LD4(sm, base);
        #pragma unroll
        for (int k = 0; k < 8; k++) {
            float4 n = LD4(sm, base + 4 * k + 4);
            float s5 = (km1.z + km1.w) + (c.x + c.y) + c.z;
            float r;
            r = c.x - 0.2f * s5; s2 += r; ss2 += r * r;
            s5 += c.w - km1.z;
            r = c.y - 0.2f * s5; s2 += r; ss2 += r * r;
            s5 += n.x - km1.w;
            r = c.z - 0.2f * s5; s2 += r; ss2 += r * r;
            s5 += n.y - c.x;
            r = c.w - 0.2f * s5; s2 += r; ss2 += r * r;
            km1 = c; c = n;
        }
    }
    const float thr2 = cluster_threshold(cl, s2, ss2, sm, rank, tid);  // sync #3

    // ===== update2 -> global ==================================================
    {
        const float thr = thr2;
        float4 lm = LD4(sm, base - 8);   // .w = e[-5]; cells -8..-6 are pad
        float4 l  = LD4(sm, base - 4);
        float4 a  = LD4(sm, base);
        float4 b  = LD4(sm, base + 4);
        float4 qm1 = l;
        float  em5 = lm.w;

        float4* go = reinterpret_cast<float4*>(out + (size_t)row * ROW_LEN + e0);
        #pragma unroll
        for (int k = 0; k < 8; k++) {
            float4 n = LD4(sm, base + 4 * k + 8);
            float s5  = (qm1.z + qm1.w) + (a.x + a.y) + a.z;
            float s11 = ((em5 + qm1.x) + (qm1.y + qm1.z)) +
                        ((qm1.w + a.x) + (a.y + a.z)) +
                        ((a.w + b.x) + b.y);
            float4 o4;
            EMIT(o4.x, a.x);  s5 += a.w - qm1.z;  s11 += b.z - em5;
            EMIT(o4.y, a.y);  s5 += b.x - qm1.w;  s11 += b.w - qm1.x;
            EMIT(o4.z, a.z);  s5 += b.y - a.x;    s11 += n.x - qm1.y;
            EMIT(o4.w, a.w);
            go[k] = o4;
            em5 = qm1.w; qm1 = a; a = b; b = n;
        }
    }
    // After thr2's internal cl.sync (last cross-CTA interaction: halo pulls
    // precede it, update2 reads only own SMEM) -> safe to exit, no trailing sync.
}

extern "C" void kernel_launch(void* const* d_in, const int* in_sizes, int n_in,
                              void* d_out, int out_size)
{
    const float* x = (const float*)d_in[0];
    float* out = (float*)d_out;
    const int rows = in_sizes[0] / ROW_LEN;   // 512

    cudaFuncSetAttribute(fd16_kernel,
                         cudaFuncAttributeMaxDynamicSharedMemorySize, SMEM_BYTES);
    fd16_kernel<<<rows * CSIZE, THREADS, SMEM_BYTES>>>(x, out);
}

// round 17
// speedup vs baseline: 1.1994x; 1.1994x over previous
#include <cuda_runtime.h>
#include <cooperative_groups.h>
#include <math.h>

namespace cg = cooperative_groups;

#define ROW_LEN   65536
#define CSIZE     8
#define SEG       (ROW_LEN / CSIZE)     // 8192 elements per CTA
#define THREADS   256
#define TPT       32                    // thread streams [e0, e0+32)
#define JOFF      8

#define TREND_SCALING       0.6f
#define DETAIL_PRESERVATION 0.85f
#define SPIKE_THRESHOLD     3.5f
#define SPIKE_DAMPING       0.35f
#define EPS_STD             1e-6f
#define F_KEEP   DETAIL_PRESERVATION                      // 0.85
#define F_DAMP   (DETAIL_PRESERVATION * SPIKE_DAMPING)    // 0.2975
#define C5       ((1.0f - TREND_SCALING) * 0.2f)          // 0.08
#define C11      (TREND_SCALING / 11.0f)

// XOR swizzle: permutes quads within 128B rows by row index; all float4
// LDS/STS at per-lane stride of 32 floats are bank-conflict-free.
__device__ __forceinline__ int SX(int j) { return j ^ ((j >> 3) & 0x1C); }

// smem layout (floats): data cells j in [0, 8224), then scratch
#define OFF_RED     8224                // 17 floats: warp partials + thr
#define OFF_MAIL    8244                // 16 floats: per-rank (s, ss)
#define SMEM_FLOATS 8260
#define SMEM_BYTES  (SMEM_FLOATS * 4)

__device__ __forceinline__ float4 LD4(const float* sm, int j) {
    return *reinterpret_cast<const float4*>(sm + SX(j));
}
__device__ __forceinline__ void ST4(float* sm, int j, float4 v) {
    *reinterpret_cast<float4*>(sm + SX(j)) = v;
}

// reflect over the full row [0, ROW_LEN)
__device__ __forceinline__ int rrow(int g) {
    if (g < 0) g = -g;
    if (g >= ROW_LEN) g = 2 * ROW_LEN - 2 - g;
    return g;
}

// cluster-wide threshold from per-thread (s, ss); deterministic order.
__device__ __forceinline__ float cluster_threshold(
    cg::cluster_group& cl, float s, float ss, float* sm, int rank, int tid)
{
    float* red  = sm + OFF_RED;
    float* mail = sm + OFF_MAIL;
    const unsigned m = 0xffffffffu;
    #pragma unroll
    for (int off = 16; off; off >>= 1) {
        s  += __shfl_down_sync(m, s,  off);
        ss += __shfl_down_sync(m, ss, off);
    }
    const int wid = tid >> 5, lid = tid & 31;
    if (lid == 0) { red[wid] = s; red[8 + wid] = ss; }
    __syncthreads();
    if (tid == 0) {
        float bs = 0.f, bss = 0.f;
        #pragma unroll
        for (int w = 0; w < 8; w++) { bs += red[w]; bss += red[8 + w]; }
        #pragma unroll
        for (int r2 = 0; r2 < CSIZE; r2++) {
            float* pm = cl.map_shared_rank(sm, r2) + OFF_MAIL;
            pm[2 * rank]     = bs;
            pm[2 * rank + 1] = bss;
        }
    }
    cl.sync();
    if (tid == 0) {
        float cs = 0.f, css = 0.f;
        #pragma unroll
        for (int r2 = 0; r2 < CSIZE; r2++) {
            cs  += mail[2 * r2];
            css += mail[2 * r2 + 1];
        }
        const float n = (float)ROW_LEN;
        float var = (css - cs * cs / n) / (n - 1.0f);
        var = fmaxf(var, 0.0f);
        red[16] = fmaxf(sqrtf(var), EPS_STD) * SPIKE_THRESHOLD;
    }
    __syncthreads();
    return red[16];
}

#define EMIT(dst, cur)                                             \
    do {                                                           \
        float _r = (cur) - 0.2f * s5;                              \
        float _f = (fabsf(_r) > thr) ? F_DAMP : F_KEEP;            \
        float _c = fmaf(s5, C5, s11 * C11);                        \
        dst = fmaf(_r, _f, _c);                                    \
    } while (0)

__global__ void __launch_bounds__(THREADS, 4) __cluster_dims__(CSIZE, 1, 1)
fd17_kernel(const float* __restrict__ x, float* __restrict__ out)
{
    extern __shared__ float sm[];
    cg::cluster_group cl = cg::this_cluster();
    const int rank = (int)cl.block_rank();
    const int row  = blockIdx.x / CSIZE;
    const int tid  = threadIdx.x;
    const float* xr = x + (size_t)row * ROW_LEN;
    const int e0   = rank * SEG + tid * TPT;   // row-local element 0
    const int base = JOFF + tid * TPT;         // smem cell of element 0

    // ---- stage segment (pure, full-MLP: 8 independent LDG.128 -> STS.128) ----
    {
        const float4* gx = reinterpret_cast<const float4*>(xr + rank * SEG);
        #pragma unroll
        for (int g = 0; g < SEG / (THREADS * 4); g++) {     // 8
            int q = g * (THREADS * 4) + tid * 4;
            ST4(sm, JOFF + q, gx[q >> 2]);
        }
    }
    __syncthreads();   // staged x visible CTA-wide

    // ---- stats1: quad-reset LDS stream; edges straight from global x ----
    float s1 = 0.f, ss1 = 0.f;
    {
        float4 km1 = (tid == 0)
            ? make_float4(0.f, 0.f, xr[rrow(e0 - 2)], xr[rrow(e0 - 1)])
            : LD4(sm, base - 4);
        float4 n7 = (tid == THREADS - 1)
            ? make_float4(xr[rrow(e0 + 32)], xr[rrow(e0 + 33)], 0.f, 0.f)
            : LD4(sm, base + 32);
        float4 c = LD4(sm, base);
        #pragma unroll
        for (int k = 0; k < 8; k++) {
            float4 n = (k < 7) ? LD4(sm, base + 4 * k + 4) : n7;
            float s5 = (km1.z + km1.w) + (c.x + c.y) + c.z;   // fresh per quad
            float r;
            r = c.x - 0.2f * s5; s1 += r; ss1 += r * r;
            s5 += c.w - km1.z;
            r = c.y - 0.2f * s5; s1 += r; ss1 += r * r;
            s5 += n.x - km1.w;
            r = c.z - 0.2f * s5; s1 += r; ss1 += r * r;
            s5 += n.y - c.x;
            r = c.w - 0.2f * s5; s1 += r; ss1 += r * r;
            km1 = c; c = n;
        }
    }
    const float thr1 = cluster_threshold(cl, s1, ss1, sm, rank, tid);  // csync #1

    // ---- update1: in-place; edge threads take x halos from global ----
    {
        const float thr = thr1;
        float4 lm, l, r6, r7;
        if (tid == 0) {
            lm = make_float4(xr[rrow(e0-8)], xr[rrow(e0-7)], xr[rrow(e0-6)], xr[rrow(e0-5)]);
            l  = make_float4(xr[rrow(e0-4)], xr[rrow(e0-3)], xr[rrow(e0-2)], xr[rrow(e0-1)]);
        } else {
            lm = LD4(sm, base - 8);
            l  = LD4(sm, base - 4);
        }
        if (tid == THREADS - 1) {
            r6 = make_float4(xr[rrow(e0+32)], xr[rrow(e0+33)], xr[rrow(e0+34)], xr[rrow(e0+35)]);
            r7 = make_float4(xr[rrow(e0+36)], xr[rrow(e0+37)], xr[rrow(e0+38)], xr[rrow(e0+39)]);
        } else {
            r6 = LD4(sm, base + 32);
            r7 = LD4(sm, base + 36);
        }
        __syncthreads();   // all cross-thread old-x reads complete before stores

        float4 a = LD4(sm, base);
        float4 b = LD4(sm, base + 4);
        float4 qm1 = l;
        float  em5 = lm.w;

        #pragma unroll
        for (int k = 0; k < 8; k++) {
            float4 n = (k < 6) ? LD4(sm, base + 4 * k + 8)
                               : ((k == 6) ? r6 : r7);
            float s5  = (qm1.z + qm1.w) + (a.x + a.y) + a.z;
            float s11 = ((em5 + qm1.x) + (qm1.y + qm1.z)) +
                        ((qm1.w + a.x) + (a.y + a.z)) +
                        ((a.w + b.x) + b.y);
            float4 o4;
            EMIT(o4.x, a.x);  s5 += a.w - qm1.z;  s11 += b.z - em5;
            EMIT(o4.y, a.y);  s5 += b.x - qm1.w;  s11 += b.w - qm1.x;
            EMIT(o4.z, a.z);  s5 += b.y - a.x;    s11 += n.x - qm1.y;
            EMIT(o4.w, a.w);
            ST4(sm, base + 4 * k, o4);
            em5 = qm1.w; qm1 = a; a = b; b = n;
        }

        // ---- local halo synthesis: current2 boundary values computed from
        // global x + thr1 (update1 is a pure function of x, thr1). No DSMEM,
        // no cluster sync needed. Row-edge reflection falls out of rrow().
        if (tid == 0 || tid == THREADS - 1) {
            // tid 0: positions e0-5..e0-1 -> cells base-5..base-1
            // tid 255: positions e0+32..e0+36 -> cells base+32..base+36
            const int p0   = (tid == 0) ? (e0 - 5) : (e0 + TPT);
            const int cell = (tid == 0) ? (base - 5) : (base + TPT);
            float w[15];
            #pragma unroll
            for (int k = 0; k < 15; k++) w[k] = xr[rrow(p0 - 5 + k)];
            #pragma unroll
            for (int j = 0; j < 5; j++) {
                float s5  = (w[j+3] + w[j+4]) + (w[j+5] + w[j+6]) + w[j+7];
                float s11 = ((w[j] + w[j+1]) + (w[j+2] + w[j+3])) +
                            ((w[j+4] + w[j+5]) + (w[j+6] + w[j+7])) +
                            ((w[j+8] + w[j+9]) + w[j+10]);
                float o;
                EMIT(o, w[j+5]);
                sm[SX(cell + j)] = o;
            }
        }
    }
    __syncthreads();   // current2 (incl. locally-synthesized halos) visible

    // ---- stats2: quad-reset LDS stream (halo cells cover edges) ----
    float s2 = 0.f, ss2 = 0.f;
    {
        float4 km1 = LD4(sm, base - 4);
        float4 c   = LD4(sm, base);
        #pragma unroll
        for (int k = 0; k < 8; k++) {
            float4 n = LD4(sm, base + 4 * k + 4);
            float s5 = (km1.z + km1.w) + (c.x + c.y) + c.z;
            float r;
            r = c.x - 0.2f * s5; s2 += r; ss2 += r * r;
            s5 += c.w - km1.z;
            r = c.y - 0.2f * s5; s2 += r; ss2 += r * r;
            s5 += n.x - km1.w;
            r = c.z - 0.2f * s5; s2 += r; ss2 += r * r;
            s5 += n.y - c.x;
            r = c.w - 0.2f * s5; s2 += r; ss2 += r * r;
            km1 = c; c = n;
        }
    }
    const float thr2 = cluster_threshold(cl, s2, ss2, sm, rank, tid);  // csync #2

    // ---- update2 -> global ----
    {
        const float thr = thr2;
        float4 lm = LD4(sm, base - 8);   // .w = e2[-5] (synthesized halo)
        float4 l  = LD4(sm, base - 4);
        float4 a  = LD4(sm, base);
        float4 b  = LD4(sm, base + 4);
        float4 qm1 = l;
        float  em5 = lm.w;

        float4* go = reinterpret_cast<float4*>(out + (size_t)row * ROW_LEN + e0);
        #pragma unroll
        for (int k = 0; k < 8; k++) {
            float4 n = LD4(sm, base + 4 * k + 8);
            float s5  = (qm1.z + qm1.w) + (a.x + a.y) + a.z;
            float s11 = ((em5 + qm1.x) + (qm1.y + qm1.z)) +
                        ((qm1.w + a.x) + (a.y + a.z)) +
                        ((a.w + b.x) + b.y);
            float4 o4;
            EMIT(o4.x, a.x);  s5 += a.w - qm1.z;  s11 += b.z - em5;
            EMIT(o4.y, a.y);  s5 += b.x - qm1.w;  s11 += b.w - qm1.x;
            EMIT(o4.z, a.z);  s5 += b.y - a.x;    s11 += n.x - qm1.y;
            EMIT(o4.w, a.w);
            go[k] = o4;
            em5 = qm1.w; qm1 = a; a = b; b = n;
        }
    }
    // Cross-CTA access exists ONLY inside cluster_threshold (mailbox pushes),
    // each followed by its own cl.sync -> safe to exit, no trailing sync.
}

extern "C" void kernel_launch(void* const* d_in, const int* in_sizes, int n_in,
                              void* d_out, int out_size)
{
    const float* x = (const float*)d_in[0];
    float* out = (float*)d_out;
    const int rows = in_sizes[0] / ROW_LEN;   // 512

    cudaFuncSetAttribute(fd17_kernel,
                         cudaFuncAttributeMaxDynamicSharedMemorySize, SMEM_BYTES);
    fd17_kernel<<<rows * CSIZE, THREADS, SMEM_BYTES>>>(x, out);
}